// round 15
// baseline (speedup 1.0000x reference)
#include <cuda_runtime.h>
#include <cuda_bf16.h>
#include <stdint.h>

#define BN   256
#define SN   512
#define HN   512
#define VN   128
#define G4H  2048
#define GRID_L   128
#define GRID_ALL 140          // 128 LSTM + 8 proj-gemm + 4 loss
#define TPB  128
#define BAR_PAD 32            // one 128B line per counter
#define NGRP 4
#define GRP_ARRIVE 35u        // 32 LSTM + 2 proj + 1 loss

// ---- shared memory layout (dynamic) ----
#define BS_OFF    0            // B slice: 64 x 520 bf16 = 66560 B (persistent)
#define BS_STRIDE 520
#define AS_OFF    66560        // A buffer: 64 x 520 bf16 = 66560 B
#define A_STRIDE  520
#define GS_OFF    133120       // gate preacts: 64 x 68 fp32 = 17408 B (own region)
#define GS_STRIDE 68
#define PJB_OFF   150528       // proj bias: 128 float
#define SMEM_BYTES 151552      // > 113.5KB -> exactly 1 CTA/SM

// ---------------- device globals ----------------
__device__ float         g_WihT[2][VN * G4H];   // [phase][tok][ng], biases folded
__device__ __nv_bfloat16 g_projW[VN * HN];
__device__ __nv_bfloat16 g_h[2][BN * HN];       // ping-pong hidden state
__device__ float         g_logits[2][BN][VN];   // logits double buffer
__device__ int           g_tokT[2][SN][BN];     // transposed tokens
__device__ float         g_invcnt[SN];
__device__ float         g_loss;
__device__ unsigned      g_cnt[NGRP * BAR_PAD]; // per-group arrive counters

// ---------------- helpers ----------------
__device__ __forceinline__ unsigned ld_acq(const unsigned* p) {
    unsigned v;
    asm volatile("ld.acquire.gpu.global.u32 %0, [%1];" : "=r"(v) : "l"(p) : "memory");
    return v;
}

// one-round group barrier: arrive via red.release.add, poll via ld.acquire (R11-proven)
__device__ __forceinline__ void group_bar(int grp, unsigned gen) {
    __syncthreads();
    if (threadIdx.x == 0) {
        unsigned* ctr = &g_cnt[grp * BAR_PAD];
        asm volatile("red.release.gpu.global.add.u32 [%0], %1;" :: "l"(ctr), "r"(1u) : "memory");
        unsigned tgt = gen * GRP_ARRIVE;
        while (ld_acq(ctr) < tgt) {}
    }
    __syncthreads();
}

__device__ __forceinline__ void mma_bf16(float* c,
                                         uint32_t a0, uint32_t a1, uint32_t a2, uint32_t a3,
                                         uint32_t b0, uint32_t b1) {
    asm volatile(
        "mma.sync.aligned.m16n8k16.row.col.f32.bf16.bf16.f32 "
        "{%0,%1,%2,%3}, {%4,%5,%6,%7}, {%8,%9}, {%0,%1,%2,%3};\n"
        : "+f"(c[0]), "+f"(c[1]), "+f"(c[2]), "+f"(c[3])
        : "r"(a0), "r"(a1), "r"(a2), "r"(a3), "r"(b0), "r"(b1));
}

__device__ __forceinline__ void ldsm4(uint32_t* r, uint32_t addr) {
    asm volatile("ldmatrix.sync.aligned.m8n8.x4.shared.b16 {%0,%1,%2,%3}, [%4];"
                 : "=r"(r[0]), "=r"(r[1]), "=r"(r[2]), "=r"(r[3]) : "r"(addr));
}

__device__ __forceinline__ float tanh_ap(float x) {
    float y; asm("tanh.approx.f32 %0, %1;" : "=f"(y) : "f"(x)); return y;
}
__device__ __forceinline__ float sigm(float x) { return fmaf(0.5f, tanh_ap(0.5f * x), 0.5f); }

// stage one K-half of A (64 rows x 256 bf16) via cp.async; one commit group
__device__ __forceinline__ void stage_half(const __nv_bfloat16* __restrict__ src0,
                                           uint32_t asbase, int half) {
    const int tid = threadIdx.x;
    #pragma unroll
    for (int jj = 0; jj < 16; ++jj) {
        int j = jj * TPB + tid;           // 0..2047 : 64 rows x 32 chunks(16B)
        int row = j >> 5, u = j & 31;
        uint32_t dst = asbase + row * (A_STRIDE * 2) + half * 512 + u * 16;
        const void* src = (const void*)(src0 + row * HN + half * 256 + u * 8);
        asm volatile("cp.async.cg.shared.global [%0], [%1], 16;" :: "r"(dst), "l"(src));
    }
    asm volatile("cp.async.commit_group;");
}

// 16 k16 iterations, warp tile M32 x N32: 4 LDSM -> 8 HMMA per k16
__device__ __forceinline__ void mma_half(uint32_t ap0, uint32_t ap1,
                                         uint32_t bp0, uint32_t bp1,
                                         float acc[2][4][4]) {
    #pragma unroll 8
    for (int kk = 0; kk < 16; ++kk) {
        uint32_t a0[4], a1[4], b0[4], b1[4];
        ldsm4(a0, ap0); ldsm4(a1, ap1); ldsm4(b0, bp0); ldsm4(b1, bp1);
        mma_bf16(acc[0][0], a0[0], a0[1], a0[2], a0[3], b0[0], b0[1]);
        mma_bf16(acc[0][1], a0[0], a0[1], a0[2], a0[3], b0[2], b0[3]);
        mma_bf16(acc[0][2], a0[0], a0[1], a0[2], a0[3], b1[0], b1[1]);
        mma_bf16(acc[0][3], a0[0], a0[1], a0[2], a0[3], b1[2], b1[3]);
        mma_bf16(acc[1][0], a1[0], a1[1], a1[2], a1[3], b0[0], b0[1]);
        mma_bf16(acc[1][1], a1[0], a1[1], a1[2], a1[3], b0[2], b0[3]);
        mma_bf16(acc[1][2], a1[0], a1[1], a1[2], a1[3], b1[0], b1[1]);
        mma_bf16(acc[1][3], a1[0], a1[1], a1[2], a1[3], b1[2], b1[3]);
        ap0 += 32; ap1 += 32; bp0 += 32; bp1 += 32;
    }
}

// pipelined: wait half0 (half1 in flight) -> MMA half0 -> wait half1 -> MMA half1
__device__ __forceinline__ void gemm_compute(uint32_t aA0, uint32_t aA1,
                                             uint32_t bA0, uint32_t bA1,
                                             float acc[2][4][4]) {
    #pragma unroll
    for (int x = 0; x < 2; ++x)
        #pragma unroll
        for (int y = 0; y < 4; ++y)
            #pragma unroll
            for (int z = 0; z < 4; ++z) acc[x][y][z] = 0.f;
    asm volatile("cp.async.wait_group 1;" ::: "memory");
    __syncthreads();
    mma_half(aA0, aA1, bA0, bA1, acc);
    asm volatile("cp.async.wait_group 0;" ::: "memory");
    __syncthreads();
    mma_half(aA0 + 512, aA1 + 512, bA0 + 512, bA1 + 512, acc);
}

// masked NLL over 64 rows (group g), 4 warps x 16 rows
__device__ __forceinline__ void loss64(int slot, int g, float& myloss) {
    int lane = threadIdx.x & 31, warp = threadIdx.x >> 5;
    int buf = slot & 1;
    #pragma unroll
    for (int rr = 0; rr < 16; ++rr) {
        int r = g * 64 + warp * 16 + rr;
        const float* rowp = g_logits[buf][r];
        float x0 = __ldcg(rowp + lane);
        float x1 = __ldcg(rowp + lane + 32);
        float x2 = __ldcg(rowp + lane + 64);
        float x3 = __ldcg(rowp + lane + 96);
        float mx = fmaxf(fmaxf(x0, x1), fmaxf(x2, x3));
        #pragma unroll
        for (int off = 16; off > 0; off >>= 1)
            mx = fmaxf(mx, __shfl_xor_sync(0xffffffffu, mx, off));
        float sme = __expf(x0 - mx) + __expf(x1 - mx) + __expf(x2 - mx) + __expf(x3 - mx);
        #pragma unroll
        for (int off = 16; off > 0; off >>= 1)
            sme += __shfl_xor_sync(0xffffffffu, sme, off);
        if (lane == 0) {
            int tgt = g_tokT[1][slot][r];
            if (tgt != 0) {
                float lt = __ldcg(&g_logits[buf][r][tgt]);
                myloss += (mx + __logf(sme) - lt) * g_invcnt[slot];
            }
        }
    }
}

// ---------------- prep ----------------
__global__ void prep_kernel(const float* __restrict__ encWih, const float* __restrict__ encbih,
                            const float* __restrict__ encbhh,
                            const float* __restrict__ decWih, const float* __restrict__ decbih,
                            const float* __restrict__ decbhh,
                            const float* __restrict__ projW,
                            const int* __restrict__ C_idx, const int* __restrict__ E) {
    int i = blockIdx.x * blockDim.x + threadIdx.x;
    if (i < VN * G4H) {
        int tok = i >> 11, ng = i & 2047;
        g_WihT[0][i] = encWih[ng * VN + tok] + encbih[ng] + encbhh[ng];
        g_WihT[1][i] = decWih[ng * VN + tok] + decbih[ng] + decbhh[ng];
    }
    if (i < VN * HN) g_projW[i] = __float2bfloat16(projW[i]);
    if (i < BN * HN) g_h[0][i] = __float2bfloat16(0.0f);
    if (i < SN * BN) {
        int t = i >> 8, b = i & 255;
        g_tokT[0][t][b] = C_idx[b * SN + t];
        g_tokT[1][t][b] = E[b * (SN + 1) + t];
    }
    if (i < NGRP * BAR_PAD) g_cnt[i] = 0u;
    if (i == 0) g_loss = 0.0f;
}

__global__ void count_kernel(const int* __restrict__ E) {
    __shared__ int red[256];
    int i = blockIdx.x, b = threadIdx.x;
    red[b] = (E[b * (SN + 1) + i] != 0) ? 1 : 0;
    __syncthreads();
    for (int off = 128; off > 0; off >>= 1) {
        if (b < off) red[b] += red[b + off];
        __syncthreads();
    }
    if (b == 0) g_invcnt[i] = (red[0] > 0) ? 1.0f / (float)red[0] : 0.0f;
}

__global__ void noop_kernel() {}

// ---------------- persistent kernel ----------------
__global__ __launch_bounds__(TPB, 1) void persist_kernel(
    const float* __restrict__ encWhh, const float* __restrict__ decWhh,
    const float* __restrict__ projb) {

    extern __shared__ __align__(16) unsigned char sm[];
    __nv_bfloat16* Bs     = (__nv_bfloat16*)(sm + BS_OFF);
    float*         Gs     = (float*)(sm + GS_OFF);
    float*         sProjb = (float*)(sm + PJB_OFF);

    const int tid = threadIdx.x, lane = tid & 31, warp = tid >> 5;
    const int bid = blockIdx.x;
    const int wm = warp & 1, wn = warp >> 1;    // 2M x 2N warp grid
    const int gq = lane >> 2, t4 = lane & 3;

    const uint32_t smem_base = (uint32_t)__cvta_generic_to_shared(sm);
    const uint32_t asbase = smem_base + AS_OFF;

    // ldmatrix lane addresses
    uint32_t aA0, aA1;
    {
        int rsel = lane & 15;
        int koff = (lane >> 4) * 16;  // bytes
        aA0 = asbase + (wm * 32 + rsel) * (A_STRIDE * 2) + koff;
        aA1 = asbase + (wm * 32 + 16 + rsel) * (A_STRIDE * 2) + koff;
    }
    uint32_t bA0, bA1;
    {
        int rowbase = wn * 32 + ((lane >> 4) << 3) + (lane & 7);
        int koff = ((lane >> 3) & 1) * 16;
        bA0 = smem_base + BS_OFF + rowbase * (BS_STRIDE * 2) + koff;
        bA1 = bA0 + 16 * (BS_STRIDE * 2);
    }

    unsigned gen = 0;

    if (bid < GRID_L) {
        // =============== LSTM role ===============
        const int grp = bid >> 5, nt = bid & 31;
        const int m0 = grp * 64, hc0 = nt * 16;
        const int m = tid >> 1, cc0 = (tid & 1) * 8;   // 8 cells per thread
        float creg[8] = {0.f, 0.f, 0.f, 0.f, 0.f, 0.f, 0.f, 0.f};
        float acc[2][4][4];

        for (int phase = 0; phase < 2; ++phase) {
            const float* __restrict__ Whh  = phase ? decWhh : encWhh;
            const float* __restrict__ WihT = g_WihT[phase];

            __syncthreads();
            for (int j = tid; j < 64 * 128; j += TPB) {
                int row = j >> 7, u = j & 127;
                int grow = ((row >> 4) << 9) + hc0 + (row & 15);
                float4 v = *(const float4*)(Whh + grow * HN + u * 4);
                __nv_bfloat162* dst = (__nv_bfloat162*)(Bs + row * BS_STRIDE + u * 4);
                dst[0] = __floats2bfloat162_rn(v.x, v.y);
                dst[1] = __floats2bfloat162_rn(v.z, v.w);
            }
            __syncthreads();

            for (int t = 0; t < SN; ++t) {
                const int gstep = (phase << 9) + t;
                const int parity = gstep & 1;
                const __nv_bfloat16* __restrict__ h_in  = g_h[parity];
                __nv_bfloat16*       __restrict__ h_out = g_h[parity ^ 1];

                // 1) stage both halves of A asynchronously
                stage_half(h_in + m0 * HN, asbase, 0);
                stage_half(h_in + m0 * HN, asbase, 1);

                // 2) x-gather: 8 cols x 4 gates (overlaps copy-wait + MMA)
                int vtok = __ldg(&g_tokT[phase][t][m0 + m]);
                const float* xrow = WihT + vtok * G4H + hc0 + cc0;
                float4 xg0a = __ldg((const float4*)(xrow + 0 * HN));
                float4 xg0b = __ldg((const float4*)(xrow + 0 * HN + 4));
                float4 xg1a = __ldg((const float4*)(xrow + 1 * HN));
                float4 xg1b = __ldg((const float4*)(xrow + 1 * HN + 4));
                float4 xg2a = __ldg((const float4*)(xrow + 2 * HN));
                float4 xg2b = __ldg((const float4*)(xrow + 2 * HN + 4));
                float4 xg3a = __ldg((const float4*)(xrow + 3 * HN));
                float4 xg3b = __ldg((const float4*)(xrow + 3 * HN + 4));

                // 3) pipelined GEMM
                gemm_compute(aA0, aA1, bA0, bA1, acc);

                #pragma unroll
                for (int am = 0; am < 2; ++am) {
                    int r0 = wm * 32 + am * 16 + gq;
                    #pragma unroll
                    for (int an = 0; an < 4; ++an) {
                        int c0 = wn * 32 + an * 8 + 2 * t4;
                        Gs[r0 * GS_STRIDE + c0]           = acc[am][an][0];
                        Gs[r0 * GS_STRIDE + c0 + 1]       = acc[am][an][1];
                        Gs[(r0 + 8) * GS_STRIDE + c0]     = acc[am][an][2];
                        Gs[(r0 + 8) * GS_STRIDE + c0 + 1] = acc[am][an][3];
                    }
                }
                __syncthreads();

                // 4) pointwise gates + c/h update (8 cells/thread, vectorized)
                {
                    const float* gr = Gs + m * GS_STRIDE;
                    float4 gia = *(float4*)(gr + 0 * 16 + cc0);
                    float4 gib = *(float4*)(gr + 0 * 16 + cc0 + 4);
                    float4 gfa = *(float4*)(gr + 1 * 16 + cc0);
                    float4 gfb = *(float4*)(gr + 1 * 16 + cc0 + 4);
                    float4 gga = *(float4*)(gr + 2 * 16 + cc0);
                    float4 ggb = *(float4*)(gr + 2 * 16 + cc0 + 4);
                    float4 goa = *(float4*)(gr + 3 * 16 + cc0);
                    float4 gob = *(float4*)(gr + 3 * 16 + cc0 + 4);
                    float pi[8] = {gia.x + xg0a.x, gia.y + xg0a.y, gia.z + xg0a.z, gia.w + xg0a.w,
                                   gib.x + xg0b.x, gib.y + xg0b.y, gib.z + xg0b.z, gib.w + xg0b.w};
                    float pf[8] = {gfa.x + xg1a.x, gfa.y + xg1a.y, gfa.z + xg1a.z, gfa.w + xg1a.w,
                                   gfb.x + xg1b.x, gfb.y + xg1b.y, gfb.z + xg1b.z, gfb.w + xg1b.w};
                    float pg[8] = {gga.x + xg2a.x, gga.y + xg2a.y, gga.z + xg2a.z, gga.w + xg2a.w,
                                   ggb.x + xg2b.x, ggb.y + xg2b.y, ggb.z + xg2b.z, ggb.w + xg2b.w};
                    float po[8] = {goa.x + xg3a.x, goa.y + xg3a.y, goa.z + xg3a.z, goa.w + xg3a.w,
                                   gob.x + xg3b.x, gob.y + xg3b.y, gob.z + xg3b.z, gob.w + xg3b.w};
                    float hv[8];
                    #pragma unroll
                    for (int j = 0; j < 8; ++j) {
                        float iv = sigm(pi[j]);
                        float fv = sigm(pf[j]);
                        float gv = tanh_ap(pg[j]);
                        float ov = sigm(po[j]);
                        float cv = fv * creg[j] + iv * gv;
                        creg[j] = cv;
                        hv[j] = ov * tanh_ap(cv);
                    }
                    uint4 hw;
                    __nv_bfloat162 q0 = __floats2bfloat162_rn(hv[0], hv[1]);
                    __nv_bfloat162 q1 = __floats2bfloat162_rn(hv[2], hv[3]);
                    __nv_bfloat162 q2 = __floats2bfloat162_rn(hv[4], hv[5]);
                    __nv_bfloat162 q3 = __floats2bfloat162_rn(hv[6], hv[7]);
                    hw.x = *(uint32_t*)&q0; hw.y = *(uint32_t*)&q1;
                    hw.z = *(uint32_t*)&q2; hw.w = *(uint32_t*)&q3;
                    *(uint4*)(h_out + (m0 + m) * HN + hc0 + cc0) = hw;
                }

                ++gen; group_bar(grp, gen);
            }
        }
        ++gen; group_bar(grp, gen);   // tail barrier (gen 1025)
    } else if (bid < GRID_L + 8) {
        // =============== projection-GEMM role ===============
        const int pb = bid - GRID_L;           // 0..7
        const int grp = pb >> 1;
        const int m0p = grp * 64;              // batch rows
        const int v0  = (pb & 1) * 64;         // vocab half
        float acc[2][4][4];

        for (int j = tid; j < 64 * 64; j += TPB) {
            int row = j >> 6, u = j & 63;
            *(uint4*)(Bs + row * BS_STRIDE + u * 8) =
                __ldcg((const uint4*)(g_projW + (v0 + row) * HN + u * 8));
        }
        sProjb[tid] = projb[tid];
        __syncthreads();

        for (unsigned gs = 0; gs < 1024; ++gs) {
            if (gs >= 513) {
                int t = (int)gs - 512;            // 1..511 -> slot t-1
                int bufp = (t - 1) & 1;
                const __nv_bfloat16* __restrict__ h_in = g_h[gs & 1];
                stage_half(h_in + m0p * HN, asbase, 0);
                stage_half(h_in + m0p * HN, asbase, 1);
                gemm_compute(aA0, aA1, bA0, bA1, acc);
                #pragma unroll
                for (int am = 0; am < 2; ++am) {
                    int r0 = m0p + wm * 32 + am * 16 + gq;
                    #pragma unroll
                    for (int an = 0; an < 4; ++an) {
                        int c0 = wn * 32 + an * 8 + 2 * t4;
                        float b0 = sProjb[v0 + c0], b1 = sProjb[v0 + c0 + 1];
                        *(float2*)&g_logits[bufp][r0][v0 + c0] =
                            make_float2(acc[am][an][0] + b0, acc[am][an][1] + b1);
                        *(float2*)&g_logits[bufp][r0 + 8][v0 + c0] =
                            make_float2(acc[am][an][2] + b0, acc[am][an][3] + b1);
                    }
                }
            }
            ++gen; group_bar(grp, gen);
        }

        {   // tail: logits for h_511 (in g_h[0]) -> slot 511 (buf 1)
            stage_half(g_h[0] + m0p * HN, asbase, 0);
            stage_half(g_h[0] + m0p * HN, asbase, 1);
            gemm_compute(aA0, aA1, bA0, bA1, acc);
            const int bufp = (SN - 1) & 1;  // 1
            #pragma unroll
            for (int am = 0; am < 2; ++am) {
                int r0 = m0p + wm * 32 + am * 16 + gq;
                #pragma unroll
                for (int an = 0; an < 4; ++an) {
                    int c0 = wn * 32 + an * 8 + 2 * t4;
                    float b0 = sProjb[v0 + c0], b1 = sProjb[v0 + c0 + 1];
                    *(float2*)&g_logits[bufp][r0][v0 + c0] =
                        make_float2(acc[am][an][0] + b0, acc[am][an][1] + b1);
                    *(float2*)&g_logits[bufp][r0 + 8][v0 + c0] =
                        make_float2(acc[am][an][2] + b0, acc[am][an][3] + b1);
                }
            }
        }
        ++gen; group_bar(grp, gen);   // gen 1025
    } else {
        // =============== loss role (1 CTA per group, 64 rows) ===============
        const int grp = bid - (GRID_L + 8);
        float myloss = 0.f;

        for (unsigned gs = 0; gs < 1024; ++gs) {
            if (gs >= 514) loss64((int)gs - 514, grp, myloss);   // slots 0..509
            ++gen; group_bar(grp, gen);
        }
        loss64(510, grp, myloss);       // written epoch 1023, sealed by bar 1024
        ++gen; group_bar(grp, gen);     // gen 1025
        loss64(511, grp, myloss);       // tail logits sealed by bar 1025
        if (lane == 0) atomicAdd(&g_loss, myloss);
    }
}

__global__ void finish_kernel(float* __restrict__ out) { out[0] = g_loss; }

// ---------------- launch ----------------
extern "C" void kernel_launch(void* const* d_in, const int* in_sizes, int n_in,
                              void* d_out, int out_size) {
    (void)in_sizes; (void)n_in; (void)out_size;
    const int*   C_idx  = (const int*)d_in[0];
    const int*   E      = (const int*)d_in[1];
    const float* encWih = (const float*)d_in[2];
    const float* encWhh = (const float*)d_in[3];
    const float* encbih = (const float*)d_in[4];
    const float* encbhh = (const float*)d_in[5];
    const float* decWih = (const float*)d_in[6];
    const float* decWhh = (const float*)d_in[7];
    const float* decbih = (const float*)d_in[8];
    const float* decbhh = (const float*)d_in[9];
    const float* projW  = (const float*)d_in[10];
    const float* projb  = (const float*)d_in[11];
    float* out = (float*)d_out;

    cudaFuncSetAttribute(persist_kernel, cudaFuncAttributeMaxDynamicSharedMemorySize,
                         SMEM_BYTES);

    prep_kernel<<<2048, 256>>>(encWih, encbih, encbhh, decWih, decbih, decbhh, projW,
                               C_idx, E);
    count_kernel<<<SN, 256>>>(E);
    noop_kernel<<<1, 32>>>();   // keeps persist_kernel at captured ncu index 5
    persist_kernel<<<GRID_ALL, TPB, SMEM_BYTES>>>(encWhh, decWhh, projb);
    finish_kernel<<<1, 256>>>(out);
}

// round 16
// speedup vs baseline: 1.9367x; 1.9367x over previous
#include <cuda_runtime.h>
#include <cuda_bf16.h>
#include <stdint.h>

#define BN   256
#define SN   512
#define HN   512
#define VN   128
#define G4H  2048
#define GRID_L   128
#define GRID_ALL 140          // 128 LSTM + 8 proj-gemm + 4 loss
#define TPB  256
#define BAR_PAD 32            // one 128B line per counter
#define NGRP 4
#define GRP_ARRIVE 35u        // 32 LSTM + 2 proj + 1 loss

// ---- shared memory layout (dynamic) ----
#define BS_OFF    0            // B slice: 64 x 520 bf16 = 66560 B (persistent)
#define BS_STRIDE 520
#define AS_OFF    66560        // A buffer: 64 x 520 bf16 = 66560 B
#define A_STRIDE  520
#define GS_OFF    133120       // gate preacts: 64 x 68 fp32 = 17408 B (own region)
#define GS_STRIDE 68
#define PJB_OFF   150528       // proj bias: 128 float
#define SMEM_BYTES 151552      // > 113.5KB -> exactly 1 CTA/SM

// ---------------- device globals ----------------
__device__ float         g_WihT[2][VN * G4H];   // [phase][tok][ng], biases folded
__device__ __nv_bfloat16 g_projW[VN * HN];
__device__ __nv_bfloat16 g_h[2][BN * HN];       // ping-pong hidden state
__device__ float         g_logits[2][BN][VN];   // logits double buffer
__device__ int           g_tokT[2][SN][BN];     // transposed tokens
__device__ float         g_invcnt[SN];
__device__ float         g_loss;
__device__ unsigned      g_cnt[NGRP * BAR_PAD]; // per-group arrive counters

// ---------------- helpers ----------------
__device__ __forceinline__ unsigned ld_acq(const unsigned* p) {
    unsigned v;
    asm volatile("ld.acquire.gpu.global.u32 %0, [%1];" : "=r"(v) : "l"(p) : "memory");
    return v;
}

// one-round group barrier: arrive via red.release.add, poll via ld.acquire (R11-proven)
__device__ __forceinline__ void group_bar(int grp, unsigned gen) {
    __syncthreads();
    if (threadIdx.x == 0) {
        unsigned* ctr = &g_cnt[grp * BAR_PAD];
        asm volatile("red.release.gpu.global.add.u32 [%0], %1;" :: "l"(ctr), "r"(1u) : "memory");
        unsigned tgt = gen * GRP_ARRIVE;
        while (ld_acq(ctr) < tgt) {}
    }
    __syncthreads();
}

__device__ __forceinline__ void mma_bf16(float* c,
                                         uint32_t a0, uint32_t a1, uint32_t a2, uint32_t a3,
                                         uint32_t b0, uint32_t b1) {
    asm volatile(
        "mma.sync.aligned.m16n8k16.row.col.f32.bf16.bf16.f32 "
        "{%0,%1,%2,%3}, {%4,%5,%6,%7}, {%8,%9}, {%0,%1,%2,%3};\n"
        : "+f"(c[0]), "+f"(c[1]), "+f"(c[2]), "+f"(c[3])
        : "r"(a0), "r"(a1), "r"(a2), "r"(a3), "r"(b0), "r"(b1));
}

__device__ __forceinline__ void ldsm4(uint32_t* r, uint32_t addr) {
    asm volatile("ldmatrix.sync.aligned.m8n8.x4.shared.b16 {%0,%1,%2,%3}, [%4];"
                 : "=r"(r[0]), "=r"(r[1]), "=r"(r[2]), "=r"(r[3]) : "r"(addr));
}

__device__ __forceinline__ float tanh_ap(float x) {
    float y; asm("tanh.approx.f32 %0, %1;" : "=f"(y) : "f"(x)); return y;
}
__device__ __forceinline__ float sigm(float x) { return fmaf(0.5f, tanh_ap(0.5f * x), 0.5f); }

// stage one K-half of A (64 rows x 256 bf16) via cp.async; one commit group
__device__ __forceinline__ void stage_half(const __nv_bfloat16* __restrict__ src0,
                                           uint32_t asbase, int half) {
    const int tid = threadIdx.x;
    #pragma unroll
    for (int jj = 0; jj < 8; ++jj) {
        int j = jj * TPB + tid;           // 0..2047 : 64 rows x 32 chunks(16B)
        int row = j >> 5, u = j & 31;
        uint32_t dst = asbase + row * (A_STRIDE * 2) + half * 512 + u * 16;
        const void* src = (const void*)(src0 + row * HN + half * 256 + u * 8);
        asm volatile("cp.async.cg.shared.global [%0], [%1], 16;" :: "r"(dst), "l"(src));
    }
    asm volatile("cp.async.commit_group;");
}

// 16 uninterrupted k16 iterations
__device__ __forceinline__ void mma_half(uint32_t ap0, uint32_t ap1, uint32_t bp,
                                         float acc[2][2][4]) {
    #pragma unroll 8
    for (int kk = 0; kk < 16; ++kk) {
        uint32_t a0[4], a1[4], b[4];
        ldsm4(a0, ap0); ldsm4(a1, ap1); ldsm4(b, bp);
        mma_bf16(acc[0][0], a0[0], a0[1], a0[2], a0[3], b[0], b[1]);
        mma_bf16(acc[0][1], a0[0], a0[1], a0[2], a0[3], b[2], b[3]);
        mma_bf16(acc[1][0], a1[0], a1[1], a1[2], a1[3], b[0], b[1]);
        mma_bf16(acc[1][1], a1[0], a1[1], a1[2], a1[3], b[2], b[3]);
        ap0 += 32; ap1 += 32; bp += 32;
    }
}

// pipelined: wait half0 (half1 in flight) -> MMA half0 -> wait half1 -> MMA half1
__device__ __forceinline__ void gemm_compute(uint32_t aA0, uint32_t aA1, uint32_t bAddr,
                                             float acc[2][2][4]) {
    #pragma unroll
    for (int x = 0; x < 2; ++x)
        #pragma unroll
        for (int y = 0; y < 2; ++y)
            #pragma unroll
            for (int z = 0; z < 4; ++z) acc[x][y][z] = 0.f;
    asm volatile("cp.async.wait_group 1;" ::: "memory");
    __syncthreads();
    mma_half(aA0, aA1, bAddr, acc);
    asm volatile("cp.async.wait_group 0;" ::: "memory");
    __syncthreads();
    mma_half(aA0 + 512, aA1 + 512, bAddr + 512, acc);
}

// masked NLL over 64 rows (group g), 8 warps x 8 rows
__device__ __forceinline__ void loss64(int slot, int g, float& myloss) {
    int lane = threadIdx.x & 31, warp = threadIdx.x >> 5;
    int buf = slot & 1;
    #pragma unroll
    for (int rr = 0; rr < 8; ++rr) {
        int r = g * 64 + warp * 8 + rr;
        const float* rowp = g_logits[buf][r];
        float x0 = __ldcg(rowp + lane);
        float x1 = __ldcg(rowp + lane + 32);
        float x2 = __ldcg(rowp + lane + 64);
        float x3 = __ldcg(rowp + lane + 96);
        float mx = fmaxf(fmaxf(x0, x1), fmaxf(x2, x3));
        #pragma unroll
        for (int off = 16; off > 0; off >>= 1)
            mx = fmaxf(mx, __shfl_xor_sync(0xffffffffu, mx, off));
        float sme = __expf(x0 - mx) + __expf(x1 - mx) + __expf(x2 - mx) + __expf(x3 - mx);
        #pragma unroll
        for (int off = 16; off > 0; off >>= 1)
            sme += __shfl_xor_sync(0xffffffffu, sme, off);
        if (lane == 0) {
            int tgt = g_tokT[1][slot][r];
            if (tgt != 0) {
                float lt = __ldcg(&g_logits[buf][r][tgt]);
                myloss += (mx + __logf(sme) - lt) * g_invcnt[slot];
            }
        }
    }
}

// ---------------- prep ----------------
__global__ void prep_kernel(const float* __restrict__ encWih, const float* __restrict__ encbih,
                            const float* __restrict__ encbhh,
                            const float* __restrict__ decWih, const float* __restrict__ decbih,
                            const float* __restrict__ decbhh,
                            const float* __restrict__ projW,
                            const int* __restrict__ C_idx, const int* __restrict__ E) {
    int i = blockIdx.x * blockDim.x + threadIdx.x;
    if (i < VN * G4H) {
        int tok = i >> 11, ng = i & 2047;
        g_WihT[0][i] = encWih[ng * VN + tok] + encbih[ng] + encbhh[ng];
        g_WihT[1][i] = decWih[ng * VN + tok] + decbih[ng] + decbhh[ng];
    }
    if (i < VN * HN) g_projW[i] = __float2bfloat16(projW[i]);
    if (i < BN * HN) g_h[0][i] = __float2bfloat16(0.0f);
    if (i < SN * BN) {
        int t = i >> 8, b = i & 255;
        g_tokT[0][t][b] = C_idx[b * SN + t];
        g_tokT[1][t][b] = E[b * (SN + 1) + t];
    }
    if (i < NGRP * BAR_PAD) g_cnt[i] = 0u;
    if (i == 0) g_loss = 0.0f;
}

__global__ void count_kernel(const int* __restrict__ E) {
    __shared__ int red[256];
    int i = blockIdx.x, b = threadIdx.x;
    red[b] = (E[b * (SN + 1) + i] != 0) ? 1 : 0;
    __syncthreads();
    for (int off = 128; off > 0; off >>= 1) {
        if (b < off) red[b] += red[b + off];
        __syncthreads();
    }
    if (b == 0) g_invcnt[i] = (red[0] > 0) ? 1.0f / (float)red[0] : 0.0f;
}

__global__ void noop_kernel() {}

// ---------------- persistent kernel ----------------
__global__ __launch_bounds__(TPB, 1) void persist_kernel(
    const float* __restrict__ encWhh, const float* __restrict__ decWhh,
    const float* __restrict__ projb) {

    extern __shared__ __align__(16) unsigned char sm[];
    __nv_bfloat16* Bs     = (__nv_bfloat16*)(sm + BS_OFF);
    float*         Gs     = (float*)(sm + GS_OFF);
    float*         sProjb = (float*)(sm + PJB_OFF);

    const int tid = threadIdx.x, lane = tid & 31, warp = tid >> 5;
    const int bid = blockIdx.x;
    const int wm = warp >> 2, wn = warp & 3;
    const int gq = lane >> 2, t4 = lane & 3;

    const uint32_t smem_base = (uint32_t)__cvta_generic_to_shared(sm);
    const uint32_t asbase = smem_base + AS_OFF;

    // ldmatrix lane addresses
    uint32_t aA0, aA1;
    {
        int rsel = lane & 15;
        int koff = (lane >> 4) * 16;  // bytes
        aA0 = asbase + (wm * 32 + rsel) * (A_STRIDE * 2) + koff;
        aA1 = asbase + (wm * 32 + 16 + rsel) * (A_STRIDE * 2) + koff;
    }
    uint32_t bAddr;
    {
        int row = wn * 16 + ((lane >> 4) << 3) + (lane & 7);
        int koff = ((lane >> 3) & 1) * 16;
        bAddr = smem_base + BS_OFF + row * (BS_STRIDE * 2) + koff;
    }

    unsigned gen = 0;

    if (bid < GRID_L) {
        // =============== LSTM role ===============
        const int grp = bid >> 5, nt = bid & 31;
        const int m0 = grp * 64, hc0 = nt * 16;
        const int m = tid >> 2, cc0 = (tid & 3) * 4;
        float creg[4] = {0.f, 0.f, 0.f, 0.f};
        float acc[2][2][4];
        float4 xi, xf, xg, xo;          // prefetched x for the CURRENT step

        // prefetch x for gstep 0 (phase 0, t 0)
        {
            int vtok = __ldg(&g_tokT[0][0][m0 + m]);
            const float* xrow = g_WihT[0] + vtok * G4H;
            xi = __ldg((const float4*)(xrow + 0 * HN + hc0 + cc0));
            xf = __ldg((const float4*)(xrow + 1 * HN + hc0 + cc0));
            xg = __ldg((const float4*)(xrow + 2 * HN + hc0 + cc0));
            xo = __ldg((const float4*)(xrow + 3 * HN + hc0 + cc0));
        }

        for (int gstep = 0; gstep < 1024; ++gstep) {
            const int phase = gstep >> 9;
            const int t = gstep & 511;
            const int parity = gstep & 1;
            const __nv_bfloat16* __restrict__ h_in  = g_h[parity];
            __nv_bfloat16*       __restrict__ h_out = g_h[parity ^ 1];

            if (t == 0) {
                // (re)load persistent W_hh slice for this phase
                const float* __restrict__ Whh = phase ? decWhh : encWhh;
                __syncthreads();
                for (int j = tid; j < 64 * 128; j += TPB) {
                    int row = j >> 7, u = j & 127;
                    int grow = ((row >> 4) << 9) + hc0 + (row & 15);
                    float4 v = *(const float4*)(Whh + grow * HN + u * 4);
                    __nv_bfloat162* dst = (__nv_bfloat162*)(Bs + row * BS_STRIDE + u * 4);
                    dst[0] = __floats2bfloat162_rn(v.x, v.y);
                    dst[1] = __floats2bfloat162_rn(v.z, v.w);
                }
                __syncthreads();
            }

            // 1) stage both halves of A asynchronously
            stage_half(h_in + m0 * HN, asbase, 0);
            stage_half(h_in + m0 * HN, asbase, 1);

            // 2) pipelined GEMM (x for this step already prefetched last iteration)
            gemm_compute(aA0, aA1, bAddr, acc);

            #pragma unroll
            for (int am = 0; am < 2; ++am) {
                int r0 = wm * 32 + am * 16 + gq;
                #pragma unroll
                for (int an = 0; an < 2; ++an) {
                    int c0 = wn * 16 + an * 8 + 2 * t4;
                    Gs[r0 * GS_STRIDE + c0]           = acc[am][an][0];
                    Gs[r0 * GS_STRIDE + c0 + 1]       = acc[am][an][1];
                    Gs[(r0 + 8) * GS_STRIDE + c0]     = acc[am][an][2];
                    Gs[(r0 + 8) * GS_STRIDE + c0 + 1] = acc[am][an][3];
                }
            }
            __syncthreads();

            // 3) pointwise gates + c/h update
            {
                float4 gi = *(float4*)(Gs + m * GS_STRIDE + 0 * 16 + cc0);
                float4 gf = *(float4*)(Gs + m * GS_STRIDE + 1 * 16 + cc0);
                float4 gg = *(float4*)(Gs + m * GS_STRIDE + 2 * 16 + cc0);
                float4 go = *(float4*)(Gs + m * GS_STRIDE + 3 * 16 + cc0);
                float pi[4] = {gi.x + xi.x, gi.y + xi.y, gi.z + xi.z, gi.w + xi.w};
                float pf[4] = {gf.x + xf.x, gf.y + xf.y, gf.z + xf.z, gf.w + xf.w};
                float pg[4] = {gg.x + xg.x, gg.y + xg.y, gg.z + xg.z, gg.w + xg.w};
                float po[4] = {go.x + xo.x, go.y + xo.y, go.z + xo.z, go.w + xo.w};
                float hv[4];
                #pragma unroll
                for (int j = 0; j < 4; ++j) {
                    float iv = sigm(pi[j]);
                    float fv = sigm(pf[j]);
                    float gv = tanh_ap(pg[j]);
                    float ov = sigm(po[j]);
                    float cv = fv * creg[j] + iv * gv;
                    creg[j] = cv;
                    hv[j] = ov * tanh_ap(cv);
                }
                __nv_bfloat162 p0 = __floats2bfloat162_rn(hv[0], hv[1]);
                __nv_bfloat162 p1 = __floats2bfloat162_rn(hv[2], hv[3]);
                uint2 hw;
                hw.x = *(uint32_t*)&p0; hw.y = *(uint32_t*)&p1;
                *(uint2*)(h_out + (m0 + m) * HN + hc0 + cc0) = hw;
            }

            // 4) prefetch x for the NEXT step: loads fly during barrier + next staging
            if (gstep < 1023) {
                int np = (gstep + 1) >> 9, ntt = (gstep + 1) & 511;
                int vtok = __ldg(&g_tokT[np][ntt][m0 + m]);
                const float* xrow = g_WihT[np] + vtok * G4H;
                xi = __ldg((const float4*)(xrow + 0 * HN + hc0 + cc0));
                xf = __ldg((const float4*)(xrow + 1 * HN + hc0 + cc0));
                xg = __ldg((const float4*)(xrow + 2 * HN + hc0 + cc0));
                xo = __ldg((const float4*)(xrow + 3 * HN + hc0 + cc0));
            }

            ++gen; group_bar(grp, gen);
        }
        ++gen; group_bar(grp, gen);   // tail barrier (gen 1025)
    } else if (bid < GRID_L + 8) {
        // =============== projection-GEMM role ===============
        const int pb = bid - GRID_L;           // 0..7
        const int grp = pb >> 1;
        const int m0p = grp * 64;              // batch rows
        const int v0  = (pb & 1) * 64;         // vocab half
        float acc[2][2][4];

        for (int j = tid; j < 64 * 64; j += TPB) {
            int row = j >> 6, u = j & 63;
            *(uint4*)(Bs + row * BS_STRIDE + u * 8) =
                __ldcg((const uint4*)(g_projW + (v0 + row) * HN + u * 8));
        }
        if (tid < 128) sProjb[tid] = projb[tid];
        __syncthreads();

        for (unsigned gs = 0; gs < 1024; ++gs) {
            if (gs >= 513) {
                int t = (int)gs - 512;            // 1..511 -> slot t-1
                int bufp = (t - 1) & 1;
                const __nv_bfloat16* __restrict__ h_in = g_h[gs & 1];
                stage_half(h_in + m0p * HN, asbase, 0);
                stage_half(h_in + m0p * HN, asbase, 1);
                gemm_compute(aA0, aA1, bAddr, acc);
                #pragma unroll
                for (int am = 0; am < 2; ++am) {
                    int r0 = m0p + wm * 32 + am * 16 + gq;
                    #pragma unroll
                    for (int an = 0; an < 2; ++an) {
                        int c0 = wn * 16 + an * 8 + 2 * t4;
                        float b0 = sProjb[v0 + c0], b1 = sProjb[v0 + c0 + 1];
                        *(float2*)&g_logits[bufp][r0][v0 + c0] =
                            make_float2(acc[am][an][0] + b0, acc[am][an][1] + b1);
                        *(float2*)&g_logits[bufp][r0 + 8][v0 + c0] =
                            make_float2(acc[am][an][2] + b0, acc[am][an][3] + b1);
                    }
                }
            }
            ++gen; group_bar(grp, gen);
        }

        {   // tail: logits for h_511 (in g_h[0]) -> slot 511 (buf 1)
            stage_half(g_h[0] + m0p * HN, asbase, 0);
            stage_half(g_h[0] + m0p * HN, asbase, 1);
            gemm_compute(aA0, aA1, bAddr, acc);
            const int bufp = (SN - 1) & 1;  // 1
            #pragma unroll
            for (int am = 0; am < 2; ++am) {
                int r0 = m0p + wm * 32 + am * 16 + gq;
                #pragma unroll
                for (int an = 0; an < 2; ++an) {
                    int c0 = wn * 16 + an * 8 + 2 * t4;
                    float b0 = sProjb[v0 + c0], b1 = sProjb[v0 + c0 + 1];
                    *(float2*)&g_logits[bufp][r0][v0 + c0] =
                        make_float2(acc[am][an][0] + b0, acc[am][an][1] + b1);
                    *(float2*)&g_logits[bufp][r0 + 8][v0 + c0] =
                        make_float2(acc[am][an][2] + b0, acc[am][an][3] + b1);
                }
            }
        }
        ++gen; group_bar(grp, gen);   // gen 1025
    } else {
        // =============== loss role (1 CTA per group, 64 rows) ===============
        const int grp = bid - (GRID_L + 8);
        float myloss = 0.f;

        for (unsigned gs = 0; gs < 1024; ++gs) {
            if (gs >= 514) loss64((int)gs - 514, grp, myloss);   // slots 0..509
            ++gen; group_bar(grp, gen);
        }
        loss64(510, grp, myloss);       // written epoch 1023, sealed by bar 1024
        ++gen; group_bar(grp, gen);     // gen 1025
        loss64(511, grp, myloss);       // tail logits sealed by bar 1025
        if (lane == 0) atomicAdd(&g_loss, myloss);
    }
}

__global__ void finish_kernel(float* __restrict__ out) { out[0] = g_loss; }

// ---------------- launch ----------------
extern "C" void kernel_launch(void* const* d_in, const int* in_sizes, int n_in,
                              void* d_out, int out_size) {
    (void)in_sizes; (void)n_in; (void)out_size;
    const int*   C_idx  = (const int*)d_in[0];
    const int*   E      = (const int*)d_in[1];
    const float* encWih = (const float*)d_in[2];
    const float* encWhh = (const float*)d_in[3];
    const float* encbih = (const float*)d_in[4];
    const float* encbhh = (const float*)d_in[5];
    const float* decWih = (const float*)d_in[6];
    const float* decWhh = (const float*)d_in[7];
    const float* decbih = (const float*)d_in[8];
    const float* decbhh = (const float*)d_in[9];
    const float* projW  = (const float*)d_in[10];
    const float* projb  = (const float*)d_in[11];
    float* out = (float*)d_out;

    cudaFuncSetAttribute(persist_kernel, cudaFuncAttributeMaxDynamicSharedMemorySize,
                         SMEM_BYTES);

    prep_kernel<<<2048, 256>>>(encWih, encbih, encbhh, decWih, decbih, decbhh, projW,
                               C_idx, E);
    count_kernel<<<SN, 256>>>(E);
    noop_kernel<<<1, 32>>>();   // keeps persist_kernel at captured ncu index 5
    persist_kernel<<<GRID_ALL, TPB, SMEM_BYTES>>>(encWhh, decWhh, projb);
    finish_kernel<<<1, 256>>>(out);
}

// round 17
// speedup vs baseline: 1.9967x; 1.0309x over previous
#include <cuda_runtime.h>
#include <cuda_bf16.h>
#include <stdint.h>

#define BN   256
#define SN   512
#define HN   512
#define VN   128
#define G4H  2048
#define GRID_L   128
#define GRID_ALL 140          // 128 LSTM + 8 proj-gemm + 4 loss
#define TPB  256
#define BAR_PAD 32            // one 128B line per counter
#define NGRP 4
#define GRP_ARRIVE 35u        // 32 LSTM + 2 proj + 1 loss

// ---- shared memory layout (dynamic) ----
#define BS_OFF    0            // B slice: 64 x 520 bf16 = 66560 B (persistent)
#define BS_STRIDE 520
#define AS_OFF    66560        // A buffer: 64 x 520 bf16 = 66560 B
#define A_STRIDE  520
#define GS_OFF    133120       // gate preacts: 64 x 68 fp32 = 17408 B (own region)
#define GS_STRIDE 68
#define PJB_OFF   150528       // proj bias: 128 float
#define SMEM_BYTES 151552      // > 113.5KB -> exactly 1 CTA/SM

// ---------------- device globals ----------------
__device__ float         g_WihT[2][VN * G4H];   // [phase][tok][ng], biases folded
__device__ __nv_bfloat16 g_projW[VN * HN];
__device__ __nv_bfloat16 g_h[2][BN * HN];       // ping-pong hidden state
__device__ float         g_logits[2][BN][VN];   // logits double buffer
__device__ int           g_tokT[2][SN][BN];     // transposed tokens
__device__ float         g_invcnt[SN];
__device__ float         g_loss;
__device__ unsigned      g_cnt[NGRP * BAR_PAD]; // per-group arrive counters

// ---------------- helpers ----------------
__device__ __forceinline__ unsigned ld_acq(const unsigned* p) {
    unsigned v;
    asm volatile("ld.acquire.gpu.global.u32 %0, [%1];" : "=r"(v) : "l"(p) : "memory");
    return v;
}

// one-round group barrier: arrive via red.release.add, poll via ld.acquire (R11-proven)
__device__ __forceinline__ void group_bar(int grp, unsigned gen) {
    __syncthreads();
    if (threadIdx.x == 0) {
        unsigned* ctr = &g_cnt[grp * BAR_PAD];
        asm volatile("red.release.gpu.global.add.u32 [%0], %1;" :: "l"(ctr), "r"(1u) : "memory");
        unsigned tgt = gen * GRP_ARRIVE;
        while (ld_acq(ctr) < tgt) {}
    }
    __syncthreads();
}

__device__ __forceinline__ void mma_bf16(float* c,
                                         uint32_t a0, uint32_t a1, uint32_t a2, uint32_t a3,
                                         uint32_t b0, uint32_t b1) {
    asm volatile(
        "mma.sync.aligned.m16n8k16.row.col.f32.bf16.bf16.f32 "
        "{%0,%1,%2,%3}, {%4,%5,%6,%7}, {%8,%9}, {%0,%1,%2,%3};\n"
        : "+f"(c[0]), "+f"(c[1]), "+f"(c[2]), "+f"(c[3])
        : "r"(a0), "r"(a1), "r"(a2), "r"(a3), "r"(b0), "r"(b1));
}

__device__ __forceinline__ void ldsm4(uint32_t* r, uint32_t addr) {
    asm volatile("ldmatrix.sync.aligned.m8n8.x4.shared.b16 {%0,%1,%2,%3}, [%4];"
                 : "=r"(r[0]), "=r"(r[1]), "=r"(r[2]), "=r"(r[3]) : "r"(addr));
}

__device__ __forceinline__ float tanh_ap(float x) {
    float y; asm("tanh.approx.f32 %0, %1;" : "=f"(y) : "f"(x)); return y;
}
__device__ __forceinline__ float sigm(float x) { return fmaf(0.5f, tanh_ap(0.5f * x), 0.5f); }

// stage one K-half of A (64 rows x 256 bf16) via cp.async; one commit group
__device__ __forceinline__ void stage_half(const __nv_bfloat16* __restrict__ src0,
                                           uint32_t asbase, int half) {
    const int tid = threadIdx.x;
    #pragma unroll
    for (int jj = 0; jj < 8; ++jj) {
        int j = jj * TPB + tid;           // 0..2047 : 64 rows x 32 chunks(16B)
        int row = j >> 5, u = j & 31;
        uint32_t dst = asbase + row * (A_STRIDE * 2) + half * 512 + u * 16;
        const void* src = (const void*)(src0 + row * HN + half * 256 + u * 8);
        asm volatile("cp.async.cg.shared.global [%0], [%1], 16;" :: "r"(dst), "l"(src));
    }
    asm volatile("cp.async.commit_group;");
}

// preload all 16 B fragments of one K-half into registers (issues during cp.async wait)
__device__ __forceinline__ void preload_B(uint32_t bp, uint32_t bf[16][4]) {
    #pragma unroll
    for (int kk = 0; kk < 16; ++kk) { ldsm4(bf[kk], bp); bp += 32; }
}

// 16 k16 iterations with PRELOADED B fragments (A LDSM only in-loop)
__device__ __forceinline__ void mma_half_pb(uint32_t ap0, uint32_t ap1,
                                            const uint32_t bf[16][4], float acc[2][2][4]) {
    #pragma unroll
    for (int kk = 0; kk < 16; ++kk) {
        uint32_t a0[4], a1[4];
        ldsm4(a0, ap0); ldsm4(a1, ap1);
        mma_bf16(acc[0][0], a0[0], a0[1], a0[2], a0[3], bf[kk][0], bf[kk][1]);
        mma_bf16(acc[0][1], a0[0], a0[1], a0[2], a0[3], bf[kk][2], bf[kk][3]);
        mma_bf16(acc[1][0], a1[0], a1[1], a1[2], a1[3], bf[kk][0], bf[kk][1]);
        mma_bf16(acc[1][1], a1[0], a1[1], a1[2], a1[3], bf[kk][2], bf[kk][3]);
        ap0 += 32; ap1 += 32;
    }
}

// 16 k16 iterations with inline B (used for half1 whose wait is short)
__device__ __forceinline__ void mma_half(uint32_t ap0, uint32_t ap1, uint32_t bp,
                                         float acc[2][2][4]) {
    #pragma unroll 8
    for (int kk = 0; kk < 16; ++kk) {
        uint32_t a0[4], a1[4], b[4];
        ldsm4(a0, ap0); ldsm4(a1, ap1); ldsm4(b, bp);
        mma_bf16(acc[0][0], a0[0], a0[1], a0[2], a0[3], b[0], b[1]);
        mma_bf16(acc[0][1], a0[0], a0[1], a0[2], a0[3], b[2], b[3]);
        mma_bf16(acc[1][0], a1[0], a1[1], a1[2], a1[3], b[0], b[1]);
        mma_bf16(acc[1][1], a1[0], a1[1], a1[2], a1[3], b[2], b[3]);
        ap0 += 32; ap1 += 32; bp += 32;
    }
}

// pipelined: preload B(half0) while cp.async half0 lands -> MMA half0 -> wait -> MMA half1
__device__ __forceinline__ void gemm_compute(uint32_t aA0, uint32_t aA1, uint32_t bAddr,
                                             float acc[2][2][4]) {
    #pragma unroll
    for (int x = 0; x < 2; ++x)
        #pragma unroll
        for (int y = 0; y < 2; ++y)
            #pragma unroll
            for (int z = 0; z < 4; ++z) acc[x][y][z] = 0.f;
    uint32_t bf[16][4];
    preload_B(bAddr, bf);              // overlaps the exposed cp.async wait below
    asm volatile("cp.async.wait_group 1;" ::: "memory");
    __syncthreads();
    mma_half_pb(aA0, aA1, bf, acc);
    asm volatile("cp.async.wait_group 0;" ::: "memory");
    __syncthreads();
    mma_half(aA0 + 512, aA1 + 512, bAddr + 512, acc);
}

// masked NLL over 64 rows (group g), 8 warps x 8 rows
__device__ __forceinline__ void loss64(int slot, int g, float& myloss) {
    int lane = threadIdx.x & 31, warp = threadIdx.x >> 5;
    int buf = slot & 1;
    #pragma unroll
    for (int rr = 0; rr < 8; ++rr) {
        int r = g * 64 + warp * 8 + rr;
        const float* rowp = g_logits[buf][r];
        float x0 = __ldcg(rowp + lane);
        float x1 = __ldcg(rowp + lane + 32);
        float x2 = __ldcg(rowp + lane + 64);
        float x3 = __ldcg(rowp + lane + 96);
        float mx = fmaxf(fmaxf(x0, x1), fmaxf(x2, x3));
        #pragma unroll
        for (int off = 16; off > 0; off >>= 1)
            mx = fmaxf(mx, __shfl_xor_sync(0xffffffffu, mx, off));
        float sme = __expf(x0 - mx) + __expf(x1 - mx) + __expf(x2 - mx) + __expf(x3 - mx);
        #pragma unroll
        for (int off = 16; off > 0; off >>= 1)
            sme += __shfl_xor_sync(0xffffffffu, sme, off);
        if (lane == 0) {
            int tgt = g_tokT[1][slot][r];
            if (tgt != 0) {
                float lt = __ldcg(&g_logits[buf][r][tgt]);
                myloss += (mx + __logf(sme) - lt) * g_invcnt[slot];
            }
        }
    }
}

// ---------------- prep ----------------
__global__ void prep_kernel(const float* __restrict__ encWih, const float* __restrict__ encbih,
                            const float* __restrict__ encbhh,
                            const float* __restrict__ decWih, const float* __restrict__ decbih,
                            const float* __restrict__ decbhh,
                            const float* __restrict__ projW,
                            const int* __restrict__ C_idx, const int* __restrict__ E) {
    int i = blockIdx.x * blockDim.x + threadIdx.x;
    if (i < VN * G4H) {
        int tok = i >> 11, ng = i & 2047;
        g_WihT[0][i] = encWih[ng * VN + tok] + encbih[ng] + encbhh[ng];
        g_WihT[1][i] = decWih[ng * VN + tok] + decbih[ng] + decbhh[ng];
    }
    if (i < VN * HN) g_projW[i] = __float2bfloat16(projW[i]);
    if (i < BN * HN) g_h[0][i] = __float2bfloat16(0.0f);
    if (i < SN * BN) {
        int t = i >> 8, b = i & 255;
        g_tokT[0][t][b] = C_idx[b * SN + t];
        g_tokT[1][t][b] = E[b * (SN + 1) + t];
    }
    if (i < NGRP * BAR_PAD) g_cnt[i] = 0u;
    if (i == 0) g_loss = 0.0f;
}

__global__ void count_kernel(const int* __restrict__ E) {
    __shared__ int red[256];
    int i = blockIdx.x, b = threadIdx.x;
    red[b] = (E[b * (SN + 1) + i] != 0) ? 1 : 0;
    __syncthreads();
    for (int off = 128; off > 0; off >>= 1) {
        if (b < off) red[b] += red[b + off];
        __syncthreads();
    }
    if (b == 0) g_invcnt[i] = (red[0] > 0) ? 1.0f / (float)red[0] : 0.0f;
}

__global__ void noop_kernel() {}

// ---------------- persistent kernel ----------------
__global__ __launch_bounds__(TPB, 1) void persist_kernel(
    const float* __restrict__ encWhh, const float* __restrict__ decWhh,
    const float* __restrict__ projb) {

    extern __shared__ __align__(16) unsigned char sm[];
    __nv_bfloat16* Bs     = (__nv_bfloat16*)(sm + BS_OFF);
    float*         Gs     = (float*)(sm + GS_OFF);
    float*         sProjb = (float*)(sm + PJB_OFF);

    const int tid = threadIdx.x, lane = tid & 31, warp = tid >> 5;
    const int bid = blockIdx.x;
    const int wm = warp >> 2, wn = warp & 3;
    const int gq = lane >> 2, t4 = lane & 3;

    const uint32_t smem_base = (uint32_t)__cvta_generic_to_shared(sm);
    const uint32_t asbase = smem_base + AS_OFF;

    // ldmatrix lane addresses
    uint32_t aA0, aA1;
    {
        int rsel = lane & 15;
        int koff = (lane >> 4) * 16;  // bytes
        aA0 = asbase + (wm * 32 + rsel) * (A_STRIDE * 2) + koff;
        aA1 = asbase + (wm * 32 + 16 + rsel) * (A_STRIDE * 2) + koff;
    }
    uint32_t bAddr;
    {
        int row = wn * 16 + ((lane >> 4) << 3) + (lane & 7);
        int koff = ((lane >> 3) & 1) * 16;
        bAddr = smem_base + BS_OFF + row * (BS_STRIDE * 2) + koff;
    }

    unsigned gen = 0;

    if (bid < GRID_L) {
        // =============== LSTM role ===============
        const int grp = bid >> 5, nt = bid & 31;
        const int m0 = grp * 64, hc0 = nt * 16;
        const int m = tid >> 2, cc0 = (tid & 3) * 4;
        float creg[4] = {0.f, 0.f, 0.f, 0.f};
        float acc[2][2][4];

        for (int phase = 0; phase < 2; ++phase) {
            const float* __restrict__ Whh  = phase ? decWhh : encWhh;
            const float* __restrict__ WihT = g_WihT[phase];

            __syncthreads();
            for (int j = tid; j < 64 * 128; j += TPB) {
                int row = j >> 7, u = j & 127;
                int grow = ((row >> 4) << 9) + hc0 + (row & 15);
                float4 v = *(const float4*)(Whh + grow * HN + u * 4);
                __nv_bfloat162* dst = (__nv_bfloat162*)(Bs + row * BS_STRIDE + u * 4);
                dst[0] = __floats2bfloat162_rn(v.x, v.y);
                dst[1] = __floats2bfloat162_rn(v.z, v.w);
            }
            __syncthreads();

            for (int t = 0; t < SN; ++t) {
                const int gstep = (phase << 9) + t;
                const int parity = gstep & 1;
                const __nv_bfloat16* __restrict__ h_in  = g_h[parity];
                __nv_bfloat16*       __restrict__ h_out = g_h[parity ^ 1];

                // 1) stage both halves of A asynchronously
                stage_half(h_in + m0 * HN, asbase, 0);
                stage_half(h_in + m0 * HN, asbase, 1);

                // 2) x-gather: overlaps copy-wait + MMA window (R11 position)
                int vtok = __ldg(&g_tokT[phase][t][m0 + m]);
                const float* xrow = WihT + vtok * G4H;
                float4 xi = __ldg((const float4*)(xrow + 0 * HN + hc0 + cc0));
                float4 xf = __ldg((const float4*)(xrow + 1 * HN + hc0 + cc0));
                float4 xg = __ldg((const float4*)(xrow + 2 * HN + hc0 + cc0));
                float4 xo = __ldg((const float4*)(xrow + 3 * HN + hc0 + cc0));

                // 3) pipelined GEMM (B half0 preloaded during copy wait)
                gemm_compute(aA0, aA1, bAddr, acc);

                #pragma unroll
                for (int am = 0; am < 2; ++am) {
                    int r0 = wm * 32 + am * 16 + gq;
                    #pragma unroll
                    for (int an = 0; an < 2; ++an) {
                        int c0 = wn * 16 + an * 8 + 2 * t4;
                        Gs[r0 * GS_STRIDE + c0]           = acc[am][an][0];
                        Gs[r0 * GS_STRIDE + c0 + 1]       = acc[am][an][1];
                        Gs[(r0 + 8) * GS_STRIDE + c0]     = acc[am][an][2];
                        Gs[(r0 + 8) * GS_STRIDE + c0 + 1] = acc[am][an][3];
                    }
                }
                __syncthreads();

                // 4) pointwise gates + c/h update
                {
                    float4 gi = *(float4*)(Gs + m * GS_STRIDE + 0 * 16 + cc0);
                    float4 gf = *(float4*)(Gs + m * GS_STRIDE + 1 * 16 + cc0);
                    float4 gg = *(float4*)(Gs + m * GS_STRIDE + 2 * 16 + cc0);
                    float4 go = *(float4*)(Gs + m * GS_STRIDE + 3 * 16 + cc0);
                    float pi[4] = {gi.x + xi.x, gi.y + xi.y, gi.z + xi.z, gi.w + xi.w};
                    float pf[4] = {gf.x + xf.x, gf.y + xf.y, gf.z + xf.z, gf.w + xf.w};
                    float pg[4] = {gg.x + xg.x, gg.y + xg.y, gg.z + xg.z, gg.w + xg.w};
                    float po[4] = {go.x + xo.x, go.y + xo.y, go.z + xo.z, go.w + xo.w};
                    float hv[4];
                    #pragma unroll
                    for (int j = 0; j < 4; ++j) {
                        float iv = sigm(pi[j]);
                        float fv = sigm(pf[j]);
                        float gv = tanh_ap(pg[j]);
                        float ov = sigm(po[j]);
                        float cv = fv * creg[j] + iv * gv;
                        creg[j] = cv;
                        hv[j] = ov * tanh_ap(cv);
                    }
                    __nv_bfloat162 p0 = __floats2bfloat162_rn(hv[0], hv[1]);
                    __nv_bfloat162 p1 = __floats2bfloat162_rn(hv[2], hv[3]);
                    uint2 hw;
                    hw.x = *(uint32_t*)&p0; hw.y = *(uint32_t*)&p1;
                    *(uint2*)(h_out + (m0 + m) * HN + hc0 + cc0) = hw;
                }

                ++gen; group_bar(grp, gen);
            }
        }
        ++gen; group_bar(grp, gen);   // tail barrier (gen 1025)
    } else if (bid < GRID_L + 8) {
        // =============== projection-GEMM role ===============
        const int pb = bid - GRID_L;           // 0..7
        const int grp = pb >> 1;
        const int m0p = grp * 64;              // batch rows
        const int v0  = (pb & 1) * 64;         // vocab half
        float acc[2][2][4];

        for (int j = tid; j < 64 * 64; j += TPB) {
            int row = j >> 6, u = j & 63;
            *(uint4*)(Bs + row * BS_STRIDE + u * 8) =
                __ldcg((const uint4*)(g_projW + (v0 + row) * HN + u * 8));
        }
        if (tid < 128) sProjb[tid] = projb[tid];
        __syncthreads();

        for (unsigned gs = 0; gs < 1024; ++gs) {
            if (gs >= 513) {
                int t = (int)gs - 512;            // 1..511 -> slot t-1
                int bufp = (t - 1) & 1;
                const __nv_bfloat16* __restrict__ h_in = g_h[gs & 1];
                stage_half(h_in + m0p * HN, asbase, 0);
                stage_half(h_in + m0p * HN, asbase, 1);
                gemm_compute(aA0, aA1, bAddr, acc);
                #pragma unroll
                for (int am = 0; am < 2; ++am) {
                    int r0 = m0p + wm * 32 + am * 16 + gq;
                    #pragma unroll
                    for (int an = 0; an < 2; ++an) {
                        int c0 = wn * 16 + an * 8 + 2 * t4;
                        float b0 = sProjb[v0 + c0], b1 = sProjb[v0 + c0 + 1];
                        *(float2*)&g_logits[bufp][r0][v0 + c0] =
                            make_float2(acc[am][an][0] + b0, acc[am][an][1] + b1);
                        *(float2*)&g_logits[bufp][r0 + 8][v0 + c0] =
                            make_float2(acc[am][an][2] + b0, acc[am][an][3] + b1);
                    }
                }
            }
            ++gen; group_bar(grp, gen);
        }

        {   // tail: logits for h_511 (in g_h[0]) -> slot 511 (buf 1)
            stage_half(g_h[0] + m0p * HN, asbase, 0);
            stage_half(g_h[0] + m0p * HN, asbase, 1);
            gemm_compute(aA0, aA1, bAddr, acc);
            const int bufp = (SN - 1) & 1;  // 1
            #pragma unroll
            for (int am = 0; am < 2; ++am) {
                int r0 = m0p + wm * 32 + am * 16 + gq;
                #pragma unroll
                for (int an = 0; an < 2; ++an) {
                    int c0 = wn * 16 + an * 8 + 2 * t4;
                    float b0 = sProjb[v0 + c0], b1 = sProjb[v0 + c0 + 1];
                    *(float2*)&g_logits[bufp][r0][v0 + c0] =
                        make_float2(acc[am][an][0] + b0, acc[am][an][1] + b1);
                    *(float2*)&g_logits[bufp][r0 + 8][v0 + c0] =
                        make_float2(acc[am][an][2] + b0, acc[am][an][3] + b1);
                }
            }
        }
        ++gen; group_bar(grp, gen);   // gen 1025
    } else {
        // =============== loss role (1 CTA per group, 64 rows) ===============
        const int grp = bid - (GRID_L + 8);
        float myloss = 0.f;

        for (unsigned gs = 0; gs < 1024; ++gs) {
            if (gs >= 514) loss64((int)gs - 514, grp, myloss);   // slots 0..509
            ++gen; group_bar(grp, gen);
        }
        loss64(510, grp, myloss);       // written epoch 1023, sealed by bar 1024
        ++gen; group_bar(grp, gen);     // gen 1025
        loss64(511, grp, myloss);       // tail logits sealed by bar 1025
        if (lane == 0) atomicAdd(&g_loss, myloss);
    }
}

__global__ void finish_kernel(float* __restrict__ out) { out[0] = g_loss; }

// ---------------- launch ----------------
extern "C" void kernel_launch(void* const* d_in, const int* in_sizes, int n_in,
                              void* d_out, int out_size) {
    (void)in_sizes; (void)n_in; (void)out_size;
    const int*   C_idx  = (const int*)d_in[0];
    const int*   E      = (const int*)d_in[1];
    const float* encWih = (const float*)d_in[2];
    const float* encWhh = (const float*)d_in[3];
    const float* encbih = (const float*)d_in[4];
    const float* encbhh = (const float*)d_in[5];
    const float* decWih = (const float*)d_in[6];
    const float* decWhh = (const float*)d_in[7];
    const float* decbih = (const float*)d_in[8];
    const float* decbhh = (const float*)d_in[9];
    const float* projW  = (const float*)d_in[10];
    const float* projb  = (const float*)d_in[11];
    float* out = (float*)d_out;

    cudaFuncSetAttribute(persist_kernel, cudaFuncAttributeMaxDynamicSharedMemorySize,
                         SMEM_BYTES);

    prep_kernel<<<2048, 256>>>(encWih, encbih, encbhh, decWih, decbih, decbhh, projW,
                               C_idx, E);
    count_kernel<<<SN, 256>>>(E);
    noop_kernel<<<1, 32>>>();   // keeps persist_kernel at captured ncu index 5
    persist_kernel<<<GRID_ALL, TPB, SMEM_BYTES>>>(encWhh, decWhh, projb);
    finish_kernel<<<1, 256>>>(out);
}